// round 2
// baseline (speedup 1.0000x reference)
#include <cuda_runtime.h>
#include <math.h>

#define NB 32
#define NT 2000
#define ED 1024
#define AD 512
#define CCH 32
#define KHALF 50
#define KW 101
#define OD 1024
#define MROWS (NB*NT)   /* 64000 */

// Scratch (device globals: allocation-free per harness rules)
__device__ float g_bias[NB*AD];        // dec_h@W_dec + b_dec + b_enc + b_att
__device__ float g_conv[NB*CCH*NT];    // location conv output [b][c][t]
__device__ float g_e[MROWS];           // pre-softmax logits (atomic accumulated)
__device__ float g_attn[MROWS];        // attention weights
__device__ float g_ctx[NB*ED];         // context vector before W_o

// ---------------------------------------------------------------------------
// Zero the accumulators (graph-safe, no memset API needed)
// ---------------------------------------------------------------------------
__global__ void zero_kernel() {
    int i = blockIdx.x * 256 + threadIdx.x;
    if (i < MROWS) g_e[i] = 0.f;
    if (i < NB*ED) g_ctx[i] = 0.f;
}

// ---------------------------------------------------------------------------
// bias[b,a] = dec_h[b,:] @ W_dec[:,a] + b_dec[a] + b_enc[a] + b_att[a]
// ---------------------------------------------------------------------------
__global__ void bias_kernel(const float* __restrict__ dec_h,
                            const float* __restrict__ W_dec,
                            const float* __restrict__ b_dec,
                            const float* __restrict__ b_enc,
                            const float* __restrict__ b_att) {
    __shared__ float ds[ED];
    int b = blockIdx.x;
    for (int d = threadIdx.x; d < ED; d += blockDim.x) ds[d] = dec_h[b*ED + d];
    __syncthreads();
    int a = threadIdx.x;  // blockDim.x == AD (512)
    float acc = b_dec[a] + b_enc[a] + b_att[a];
    #pragma unroll 8
    for (int d = 0; d < ED; d++)
        acc = fmaf(ds[d], W_dec[d*AD + a], acc);
    g_bias[b*AD + a] = acc;
}

// ---------------------------------------------------------------------------
// convout[b,c,t] = sum_k conv_w[c,k] * att_prev_pad[b, t+k-50]  (SAME, zero pad)
// ---------------------------------------------------------------------------
__global__ void conv_kernel(const float* __restrict__ att_prev,
                            const float* __restrict__ conv_w) {
    __shared__ float ap[NT];
    __shared__ float wk[KW];
    int b = blockIdx.x, c = blockIdx.y;
    for (int t = threadIdx.x; t < NT; t += blockDim.x) ap[t] = att_prev[b*NT + t];
    for (int k = threadIdx.x; k < KW; k += blockDim.x) wk[k] = conv_w[c*KW + k];
    __syncthreads();
    for (int t = threadIdx.x; t < NT; t += blockDim.x) {
        float s = 0.f;
        #pragma unroll 4
        for (int k = 0; k < KW; k++) {
            int idx = t + k - KHALF;
            if (idx >= 0 && idx < NT) s = fmaf(ap[idx], wk[k], s);
        }
        g_conv[(b*CCH + c)*NT + t] = s;
    }
}

// ---------------------------------------------------------------------------
// Fused main GEMM: e_partial = sum_a tanh(enc@W_enc + bias + convout@W_att) * g
// M = 64000 (b,t rows), N = 512 (a), K = 1024 (enc dim)
// Block tile 128x128, BK=16, 256 threads, 8x8 per-thread microtile.
// Epilogue: +32-channel conv mini-GEMM, +bias, tanh, dot with gvec,
// half-warp shuffle reduce over 16 N-lanes, atomicAdd into g_e (4 N-tiles).
// ---------------------------------------------------------------------------
__global__ __launch_bounds__(256, 2)
void gemm_e_kernel(const float* __restrict__ A,      // enc_pad [64000,1024]
                   const float* __restrict__ W,      // W_enc [1024,512]
                   const float* __restrict__ Watt,   // W_att [32,512]
                   const float* __restrict__ gv)     // gvec  [512]
{
    __shared__ float smem[8192];          // 32 KB, reused for epilogue
    __shared__ float gS[128];
    float* As = smem;                     // [16][128] (k-major, transposed)
    float* Bs = smem + 2048;              // [16][128]

    const int bx = blockIdx.x;            // N tile: 0..3
    const int by = blockIdx.y;            // M tile: 0..499
    const int tid = threadIdx.x;
    const int tx = tid & 15, ty = tid >> 4;
    const int m0 = by * 128, n0 = bx * 128;

    float acc[8][8];
    #pragma unroll
    for (int i = 0; i < 8; i++)
        #pragma unroll
        for (int j = 0; j < 8; j++) acc[i][j] = 0.f;

    for (int k0 = 0; k0 < ED; k0 += 16) {
        // load A tile: 128 rows x 16 cols = 512 float4s
        #pragma unroll
        for (int q = 0; q < 2; q++) {
            int fid = tid + q*256;
            int row = fid >> 2;
            int c4  = fid & 3;
            float4 v = *reinterpret_cast<const float4*>(&A[(size_t)(m0+row)*ED + k0 + c4*4]);
            As[(c4*4+0)*128 + row] = v.x;
            As[(c4*4+1)*128 + row] = v.y;
            As[(c4*4+2)*128 + row] = v.z;
            As[(c4*4+3)*128 + row] = v.w;
            // load B tile: 16 rows x 128 cols = 512 float4s
            int rowB = fid >> 5;
            int cB   = fid & 31;
            float4 w = *reinterpret_cast<const float4*>(&W[(k0+rowB)*AD + n0 + cB*4]);
            *reinterpret_cast<float4*>(&Bs[rowB*128 + cB*4]) = w;
        }
        __syncthreads();
        #pragma unroll
        for (int kk = 0; kk < 16; kk++) {
            float a[8], bb[8];
            float4 a0 = *reinterpret_cast<const float4*>(&As[kk*128 + ty*8]);
            float4 a1 = *reinterpret_cast<const float4*>(&As[kk*128 + ty*8 + 4]);
            float4 b0 = *reinterpret_cast<const float4*>(&Bs[kk*128 + tx*8]);
            float4 b1 = *reinterpret_cast<const float4*>(&Bs[kk*128 + tx*8 + 4]);
            a[0]=a0.x;a[1]=a0.y;a[2]=a0.z;a[3]=a0.w;a[4]=a1.x;a[5]=a1.y;a[6]=a1.z;a[7]=a1.w;
            bb[0]=b0.x;bb[1]=b0.y;bb[2]=b0.z;bb[3]=b0.w;bb[4]=b1.x;bb[5]=b1.y;bb[6]=b1.z;bb[7]=b1.w;
            #pragma unroll
            for (int i = 0; i < 8; i++)
                #pragma unroll
                for (int j = 0; j < 8; j++)
                    acc[i][j] = fmaf(a[i], bb[j], acc[i][j]);
        }
        __syncthreads();
    }

    // ---- epilogue: conv mini-GEMM (K=32) into acc ----
    float* convS = smem;          // [32][128]  (c-major, li minor)
    float* WattS = smem + 4096;   // [32][128]
    #pragma unroll
    for (int q = 0; q < 16; q++) {
        int idx = tid + q*256;            // 0..4095
        int c  = idx >> 7;
        int li = idx & 127;
        int grow = m0 + li;
        int b = grow / NT;
        int t = grow - b*NT;
        convS[c*128 + li] = g_conv[(b*CCH + c)*NT + t];
        WattS[c*128 + li] = Watt[c*AD + n0 + li];
    }
    if (tid < 128) gS[tid] = gv[n0 + tid];
    __syncthreads();

    #pragma unroll
    for (int c = 0; c < 32; c++) {
        float a[8], bb[8];
        #pragma unroll
        for (int i = 0; i < 8; i++) a[i] = convS[c*128 + ty*8 + i];
        #pragma unroll
        for (int j = 0; j < 8; j++) bb[j] = WattS[c*128 + tx*8 + j];
        #pragma unroll
        for (int i = 0; i < 8; i++)
            #pragma unroll
            for (int j = 0; j < 8; j++)
                acc[i][j] = fmaf(a[i], bb[j], acc[i][j]);
    }

    // ---- bias + tanh + gvec dot + reduce over 16 N-lanes ----
    #pragma unroll
    for (int i = 0; i < 8; i++) {
        int li = ty*8 + i;
        int grow = m0 + li;
        int b = grow / NT;
        const float* biasrow = &g_bias[b*AD + n0 + tx*8];
        float pe = 0.f;
        #pragma unroll
        for (int j = 0; j < 8; j++) {
            float v = acc[i][j] + biasrow[j];
            pe = fmaf(tanhf(v), gS[tx*8 + j], pe);
        }
        pe += __shfl_down_sync(0xffffffffu, pe, 8, 16);
        pe += __shfl_down_sync(0xffffffffu, pe, 4, 16);
        pe += __shfl_down_sync(0xffffffffu, pe, 2, 16);
        pe += __shfl_down_sync(0xffffffffu, pe, 1, 16);
        if (tx == 0) atomicAdd(&g_e[grow], pe);
    }
}

// ---------------------------------------------------------------------------
// Masked softmax over T with SCALING=2; writes g_attn (and d_out copy if set)
// ---------------------------------------------------------------------------
__global__ void softmax_kernel(const int* __restrict__ enc_len,
                               float* __restrict__ attn_dst, int write_dst) {
    __shared__ float red[256];
    int b = blockIdx.x;
    int len = enc_len[b];
    const float* e = &g_e[b*NT];

    float m = -1e30f;
    for (int t = threadIdx.x; t < NT; t += 256)
        if (t < len) m = fmaxf(m, 2.f * e[t]);
    red[threadIdx.x] = m; __syncthreads();
    for (int s = 128; s > 0; s >>= 1) {
        if (threadIdx.x < s) red[threadIdx.x] = fmaxf(red[threadIdx.x], red[threadIdx.x+s]);
        __syncthreads();
    }
    m = red[0]; __syncthreads();

    float sum = 0.f;
    for (int t = threadIdx.x; t < NT; t += 256)
        if (t < len) sum += expf(2.f * e[t] - m);
    red[threadIdx.x] = sum; __syncthreads();
    for (int s = 128; s > 0; s >>= 1) {
        if (threadIdx.x < s) red[threadIdx.x] += red[threadIdx.x+s];
        __syncthreads();
    }
    sum = red[0];
    float inv = 1.f / sum;

    for (int t = threadIdx.x; t < NT; t += 256) {
        float v = (t < len) ? expf(2.f * e[t] - m) * inv : 0.f;
        g_attn[b*NT + t] = v;
        if (write_dst) attn_dst[b*NT + t] = v;
    }
}

// ---------------------------------------------------------------------------
// ctx[b,d] = sum_t attn[b,t] * enc_pad[b,t,d]   (split over 8 t-ranges)
// ---------------------------------------------------------------------------
__global__ void ctx_kernel(const float* __restrict__ enc) {
    int b = blockIdx.x;
    int t0 = blockIdx.y * 250, t1 = t0 + 250;
    float acc[4] = {0.f, 0.f, 0.f, 0.f};
    for (int t = t0; t < t1; t++) {
        float w = g_attn[b*NT + t];
        if (w != 0.f) {
            const float* row = &enc[((size_t)b*NT + t)*ED];
            #pragma unroll
            for (int q = 0; q < 4; q++)
                acc[q] = fmaf(w, row[threadIdx.x + q*256], acc[q]);
        }
    }
    #pragma unroll
    for (int q = 0; q < 4; q++)
        atomicAdd(&g_ctx[b*ED + threadIdx.x + q*256], acc[q]);
}

// ---------------------------------------------------------------------------
// c[b,o] = ctx[b,:] @ W_o[:,o] + b_o[o]
// ---------------------------------------------------------------------------
__global__ void out_kernel(const float* __restrict__ W_o,
                           const float* __restrict__ b_o,
                           float* __restrict__ c_dst, int write_dst) {
    __shared__ float cs[ED];
    int b = blockIdx.x;
    for (int d = threadIdx.x; d < ED; d += 256) cs[d] = g_ctx[b*ED + d];
    __syncthreads();
    if (!write_dst) return;
    float acc[4];
    #pragma unroll
    for (int q = 0; q < 4; q++) acc[q] = b_o[threadIdx.x + q*256];
    for (int d = 0; d < ED; d++) {
        float cv = cs[d];
        #pragma unroll
        for (int q = 0; q < 4; q++)
            acc[q] = fmaf(cv, W_o[d*OD + threadIdx.x + q*256], acc[q]);
    }
    #pragma unroll
    for (int q = 0; q < 4; q++)
        c_dst[b*OD + threadIdx.x + q*256] = acc[q];
}

// ---------------------------------------------------------------------------
extern "C" void kernel_launch(void* const* d_in, const int* in_sizes, int n_in,
                              void* d_out, int out_size) {
    const float* enc_pad  = (const float*)d_in[0];
    const int*   enc_len  = (const int*)  d_in[1];
    const float* dec_h    = (const float*)d_in[2];
    const float* att_prev = (const float*)d_in[3];
    const float* W_enc    = (const float*)d_in[4];
    const float* b_enc    = (const float*)d_in[5];
    const float* W_dec    = (const float*)d_in[6];
    const float* b_dec    = (const float*)d_in[7];
    const float* W_att    = (const float*)d_in[8];
    const float* b_att    = (const float*)d_in[9];
    const float* conv_w   = (const float*)d_in[10];
    const float* gvec     = (const float*)d_in[11];
    const float* W_o      = (const float*)d_in[12];
    const float* b_o      = (const float*)d_in[13];

    float* out = (float*)d_out;

    // Output layout: default assumption — (c[32,1024], attn[32,2000]) flattened.
    float* c_dst    = out;
    float* attn_dst = out;
    int write_c = 0, write_attn = 0;
    if (out_size >= NB*OD + NB*NT) {            // both outputs
        c_dst = out; attn_dst = out + NB*OD;
        write_c = 1; write_attn = 1;
    } else if (out_size == NB*NT) {             // attn only
        attn_dst = out; write_attn = 1;
    } else {                                     // c only (or unknown small)
        c_dst = out; write_c = 1;
    }

    zero_kernel<<<(MROWS + 255)/256, 256>>>();
    bias_kernel<<<NB, AD>>>(dec_h, W_dec, b_dec, b_enc, b_att);
    conv_kernel<<<dim3(NB, CCH), 256>>>(att_prev, conv_w);
    gemm_e_kernel<<<dim3(4, 500), 256>>>(enc_pad, W_enc, W_att, gvec);
    softmax_kernel<<<NB, 256>>>(enc_len, attn_dst, write_attn);
    ctx_kernel<<<dim3(NB, 8), 256>>>(enc_pad);
    out_kernel<<<NB, 256>>>(W_o, b_o, c_dst, write_c);
}

// round 4
// speedup vs baseline: 2.2372x; 2.2372x over previous
#include <cuda_runtime.h>
#include <cstdint>
#include <math.h>

#define NB 32
#define NT 2000
#define ED 1024
#define AD 512
#define CCH 32
#define KHALF 50
#define KW 101
#define OD 1024
#define MROWS (NB*NT)     /* 64000 */
#define KEXT (ED + CCH)   /* 1056 */

// ---------------- device scratch (allocation-free) ----------------
__device__ __align__(128) float g_Bt[AD * KEXT];      // [n][k], tf32-rounded
__device__ __align__(128) float g_convT[MROWS * CCH]; // [row][c]
__device__ float g_bias[NB * AD];
__device__ float g_e[MROWS];
__device__ float g_attn[MROWS];
__device__ float g_ctx[NB * ED];

// ---------------- helpers ----------------
__device__ __forceinline__ void cp16(uint32_t dst, const void* src) {
    asm volatile("cp.async.cg.shared.global [%0], [%1], 16;" :: "r"(dst), "l"(src) : "memory");
}
__device__ __forceinline__ uint32_t smem_u32(const void* p) {
    uint32_t a;
    asm("{ .reg .u64 t; cvta.to.shared.u64 t, %1; cvt.u32.u64 %0, t; }" : "=r"(a) : "l"(p));
    return a;
}
__device__ __forceinline__ uint32_t tf32_rna_u(float f) {
    uint32_t u; asm("cvt.rna.tf32.f32 %0, %1;" : "=r"(u) : "f"(f)); return u;
}
__device__ __forceinline__ float tf32_rna_f(float f) {
    return __uint_as_float(tf32_rna_u(f));
}
__device__ __forceinline__ float fast_tanh(float x) {
    float y; asm("tanh.approx.f32 %0, %1;" : "=f"(y) : "f"(x)); return y;
}
__device__ __forceinline__ void mma_tf32(float& d0, float& d1, float& d2, float& d3,
                                         uint32_t a0, uint32_t a1, uint32_t a2, uint32_t a3,
                                         uint32_t b0, uint32_t b1) {
    asm volatile(
        "mma.sync.aligned.m16n8k8.row.col.f32.tf32.tf32.f32 "
        "{%0,%1,%2,%3},{%4,%5,%6,%7},{%8,%9},{%0,%1,%2,%3};"
        : "+f"(d0), "+f"(d1), "+f"(d2), "+f"(d3)
        : "r"(a0), "r"(a1), "r"(a2), "r"(a3), "r"(b0), "r"(b1));
}

// ---------------------------------------------------------------------------
// Pack B' = [W_enc ; W_att] transposed K-major, pre-rounded to tf32
// ---------------------------------------------------------------------------
__global__ void btrans_kernel(const float* __restrict__ W_enc,
                              const float* __restrict__ W_att) {
    __shared__ float sm[32][33];
    int tx = threadIdx.x, ty = threadIdx.y;
    int k = blockIdx.x * 32 + ty;
    int n = blockIdx.y * 32 + tx;
    sm[ty][tx] = (k < ED) ? W_enc[k * AD + n] : W_att[(k - ED) * AD + n];
    __syncthreads();
    g_Bt[(blockIdx.y * 32 + ty) * KEXT + blockIdx.x * 32 + tx] = tf32_rna_f(sm[tx][ty]);
}

// ---------------------------------------------------------------------------
// Location conv -> row-major channels: g_convT[(b*NT+t)*32 + c]
// ---------------------------------------------------------------------------
__global__ void conv_kernel(const float* __restrict__ att_prev,
                            const float* __restrict__ conv_w) {
    __shared__ float ap[350];
    __shared__ float wk[CCH * KW];
    int b = blockIdx.y;
    int t0 = blockIdx.x * 250;
    for (int i = threadIdx.x; i < 350; i += 256) {
        int gidx = t0 - KHALF + i;
        ap[i] = (gidx >= 0 && gidx < NT) ? att_prev[b * NT + gidx] : 0.f;
    }
    for (int i = threadIdx.x; i < CCH * KW; i += 256) wk[i] = conv_w[i];
    __syncthreads();
    int lt = threadIdx.x;
    if (lt < 250) {
        float s[CCH];
        #pragma unroll
        for (int c = 0; c < CCH; c++) s[c] = 0.f;
        for (int k = 0; k < KW; k++) {
            float av = ap[lt + k];
            #pragma unroll
            for (int c = 0; c < CCH; c++) s[c] = fmaf(av, wk[c * KW + k], s[c]);
        }
        float4* dst = reinterpret_cast<float4*>(&g_convT[(size_t)(b * NT + t0 + lt) * CCH]);
        #pragma unroll
        for (int q = 0; q < 8; q++) dst[q] = make_float4(s[4*q], s[4*q+1], s[4*q+2], s[4*q+3]);
    }
}

// ---------------------------------------------------------------------------
// bias[b,a] = dec_h[b]@W_dec + b_dec + b_enc + b_att ; also zero g_e
// ---------------------------------------------------------------------------
__global__ void bias_kernel(const float* __restrict__ dec_h,
                            const float* __restrict__ W_dec,
                            const float* __restrict__ b_dec,
                            const float* __restrict__ b_enc,
                            const float* __restrict__ b_att) {
    __shared__ float ds[ED];
    int b = blockIdx.x;
    for (int d = threadIdx.x; d < ED; d += blockDim.x) ds[d] = dec_h[b*ED + d];
    __syncthreads();
    int a = threadIdx.x;
    float acc = b_dec[a] + b_enc[a] + b_att[a];
    #pragma unroll 8
    for (int d = 0; d < ED; d++) acc = fmaf(ds[d], W_dec[d*AD + a], acc);
    g_bias[b*AD + a] = acc;
}

__global__ void zero_kernel() {
    int i = blockIdx.x * 256 + threadIdx.x;
    if (i < MROWS) g_e[i] = 0.f;
    if (i < NB*ED) g_ctx[i] = 0.f;
}

// ---------------------------------------------------------------------------
// Main GEMM via mma.sync tf32: e = sum_n tanh(A'@B' + bias) * g
// M=64000, N=512 (4 CTA blocks of 128), K'=1056 (33 tiles of 32).
// CTA: 256 thr = 8 warps (2 m x 4 n); warp tile 64x32; m16n8k8 frags.
// Smem: stride-36 layout -> conflict-free frag loads. 2-stage cp.async.
// ---------------------------------------------------------------------------
#define STAGE_B 36864          /* A 18432 + B 18432 */
#define DYN_SMEM (2*STAGE_B)

__global__ __launch_bounds__(256)
void gemm_e_mma(const float* __restrict__ enc, const float* __restrict__ gv) {
    extern __shared__ char dyn[];
    __shared__ float gS[128];
    __shared__ float biasS[2][128];
    __shared__ float e_buf[4][128];

    const int tid = threadIdx.x, lane = tid & 31, wid = tid >> 5;
    const int wm = wid >> 2, wn = wid & 3;
    const int g = lane >> 2, c4 = lane & 3;
    const int n0 = blockIdx.x * 128;
    const int m0 = blockIdx.y * 128;
    const uint32_t sbase = smem_u32(dyn);
    const int bA = m0 / NT, bB = (m0 + 127) / NT;

    if (tid < 128) {
        gS[tid] = gv[n0 + tid];
        biasS[0][tid] = g_bias[bA*AD + n0 + tid];
    } else {
        biasS[1][tid-128] = g_bias[bB*AD + n0 + tid - 128];
    }

    float d[4][4][4];
    #pragma unroll
    for (int i = 0; i < 4; i++)
        #pragma unroll
        for (int j = 0; j < 4; j++)
            #pragma unroll
            for (int q = 0; q < 4; q++) d[i][j][q] = 0.f;

    auto issue_tile = [&](int i, int s) {
        uint32_t stA = sbase + s * STAGE_B;
        uint32_t stB = stA + 18432;
        #pragma unroll
        for (int q = 0; q < 4; q++) {
            int u = q * 256 + tid;
            int row = u >> 3, c16 = u & 7;
            const float* srcA = (i < 32)
                ? enc + (size_t)(m0 + row) * ED + i * 32 + c16 * 4
                : g_convT + (size_t)(m0 + row) * CCH + c16 * 4;
            cp16(stA + row * 144 + c16 * 16, srcA);
            const float* srcB = g_Bt + (size_t)(n0 + row) * KEXT + i * 32 + c16 * 4;
            cp16(stB + row * 144 + c16 * 16, srcB);
        }
        asm volatile("cp.async.commit_group;" ::: "memory");
    };

    issue_tile(0, 0);

    for (int i = 0; i < 33; i++) {
        const int s = i & 1;
        if (i < 32) {
            issue_tile(i + 1, s ^ 1);
            asm volatile("cp.async.wait_group 1;" ::: "memory");
        } else {
            asm volatile("cp.async.wait_group 0;" ::: "memory");
        }
        __syncthreads();

        const float* As = (const float*)(dyn + s * STAGE_B);
        const float* Bs = (const float*)(dyn + s * STAGE_B + 18432);

        #pragma unroll
        for (int ks = 0; ks < 4; ks++) {
            const int k0 = ks * 8;
            uint32_t br[4][2];
            #pragma unroll
            for (int nf = 0; nf < 4; nf++) {
                int n = wn * 32 + nf * 8 + g;
                br[nf][0] = __float_as_uint(Bs[n * 36 + k0 + c4]);
                br[nf][1] = __float_as_uint(Bs[n * 36 + k0 + c4 + 4]);
            }
            #pragma unroll
            for (int mf = 0; mf < 4; mf++) {
                int r = wm * 64 + mf * 16 + g;
                uint32_t a0 = tf32_rna_u(As[r * 36 + k0 + c4]);
                uint32_t a1 = tf32_rna_u(As[(r + 8) * 36 + k0 + c4]);
                uint32_t a2 = tf32_rna_u(As[r * 36 + k0 + c4 + 4]);
                uint32_t a3 = tf32_rna_u(As[(r + 8) * 36 + k0 + c4 + 4]);
                #pragma unroll
                for (int nf = 0; nf < 4; nf++)
                    mma_tf32(d[mf][nf][0], d[mf][nf][1], d[mf][nf][2], d[mf][nf][3],
                             a0, a1, a2, a3, br[nf][0], br[nf][1]);
            }
        }
        __syncthreads();
    }

    // ---- epilogue: tanh + g-dot, reduce to e ----
    float pr[4][2];
    #pragma unroll
    for (int mf = 0; mf < 4; mf++) { pr[mf][0] = 0.f; pr[mf][1] = 0.f; }

    #pragma unroll
    for (int mf = 0; mf < 4; mf++) {
        int r_lo = wm * 64 + mf * 16 + g;
        int bi_lo = ((m0 + r_lo) / NT == bA) ? 0 : 1;
        int bi_hi = ((m0 + r_lo + 8) / NT == bA) ? 0 : 1;
        #pragma unroll
        for (int nf = 0; nf < 4; nf++) {
            #pragma unroll
            for (int j = 0; j < 4; j++) {
                int colL = wn * 32 + nf * 8 + 2 * c4 + (j & 1);
                int bi = (j >= 2) ? bi_hi : bi_lo;
                float v = d[mf][nf][j] + biasS[bi][colL];
                pr[mf][j >= 2] = fmaf(fast_tanh(v), gS[colL], pr[mf][j >= 2]);
            }
        }
    }
    #pragma unroll
    for (int mf = 0; mf < 4; mf++) {
        #pragma unroll
        for (int h = 0; h < 2; h++) {
            pr[mf][h] += __shfl_xor_sync(0xffffffffu, pr[mf][h], 1);
            pr[mf][h] += __shfl_xor_sync(0xffffffffu, pr[mf][h], 2);
        }
    }
    if (c4 == 0) {
        #pragma unroll
        for (int mf = 0; mf < 4; mf++) {
            e_buf[wn][wm * 64 + mf * 16 + g]     = pr[mf][0];
            e_buf[wn][wm * 64 + mf * 16 + g + 8] = pr[mf][1];
        }
    }
    __syncthreads();
    if (tid < 128)
        atomicAdd(&g_e[m0 + tid],
                  e_buf[0][tid] + e_buf[1][tid] + e_buf[2][tid] + e_buf[3][tid]);
}

// ---------------------------------------------------------------------------
// Masked softmax (SCALING=2)
// ---------------------------------------------------------------------------
__global__ void softmax_kernel(const int* __restrict__ enc_len,
                               float* __restrict__ attn_dst, int write_dst) {
    __shared__ float red[256];
    int b = blockIdx.x;
    int len = enc_len[b];
    const float* e = &g_e[b*NT];

    float m = -1e30f;
    for (int t = threadIdx.x; t < NT; t += 256)
        if (t < len) m = fmaxf(m, 2.f * e[t]);
    red[threadIdx.x] = m; __syncthreads();
    for (int s = 128; s > 0; s >>= 1) {
        if (threadIdx.x < s) red[threadIdx.x] = fmaxf(red[threadIdx.x], red[threadIdx.x+s]);
        __syncthreads();
    }
    m = red[0]; __syncthreads();

    float sum = 0.f;
    for (int t = threadIdx.x; t < NT; t += 256)
        if (t < len) sum += expf(2.f * e[t] - m);
    red[threadIdx.x] = sum; __syncthreads();
    for (int s = 128; s > 0; s >>= 1) {
        if (threadIdx.x < s) red[threadIdx.x] += red[threadIdx.x+s];
        __syncthreads();
    }
    float inv = 1.f / red[0];

    for (int t = threadIdx.x; t < NT; t += 256) {
        float v = (t < len) ? expf(2.f * e[t] - m) * inv : 0.f;
        g_attn[b*NT + t] = v;
        if (write_dst) attn_dst[b*NT + t] = v;
    }
}

// ---------------------------------------------------------------------------
// ctx[b,d] = sum_t attn[b,t] * enc[b,t,d]
// ---------------------------------------------------------------------------
__global__ void ctx_kernel(const float* __restrict__ enc) {
    int b = blockIdx.x;
    int t0 = blockIdx.y * 250, t1 = t0 + 250;
    float acc[4] = {0.f, 0.f, 0.f, 0.f};
    for (int t = t0; t < t1; t++) {
        float w = g_attn[b*NT + t];
        if (w != 0.f) {
            const float* row = &enc[((size_t)b*NT + t)*ED];
            #pragma unroll
            for (int q = 0; q < 4; q++)
                acc[q] = fmaf(w, row[threadIdx.x + q*256], acc[q]);
        }
    }
    #pragma unroll
    for (int q = 0; q < 4; q++)
        atomicAdd(&g_ctx[b*ED + threadIdx.x + q*256], acc[q]);
}

// ---------------------------------------------------------------------------
// c[b,o] = ctx[b]@W_o + b_o
// ---------------------------------------------------------------------------
__global__ void out_kernel(const float* __restrict__ W_o,
                           const float* __restrict__ b_o,
                           float* __restrict__ c_dst, int write_dst) {
    __shared__ float cs[ED];
    int b = blockIdx.x;
    for (int d = threadIdx.x; d < ED; d += 256) cs[d] = g_ctx[b*ED + d];
    __syncthreads();
    if (!write_dst) return;
    float acc[4];
    #pragma unroll
    for (int q = 0; q < 4; q++) acc[q] = b_o[threadIdx.x + q*256];
    for (int d = 0; d < ED; d++) {
        float cv = cs[d];
        #pragma unroll
        for (int q = 0; q < 4; q++)
            acc[q] = fmaf(cv, W_o[d*OD + threadIdx.x + q*256], acc[q]);
    }
    #pragma unroll
    for (int q = 0; q < 4; q++)
        c_dst[b*OD + threadIdx.x + q*256] = acc[q];
}

// ---------------------------------------------------------------------------
extern "C" void kernel_launch(void* const* d_in, const int* in_sizes, int n_in,
                              void* d_out, int out_size) {
    const float* enc_pad  = (const float*)d_in[0];
    const int*   enc_len  = (const int*)  d_in[1];
    const float* dec_h    = (const float*)d_in[2];
    const float* att_prev = (const float*)d_in[3];
    const float* W_enc    = (const float*)d_in[4];
    const float* b_enc    = (const float*)d_in[5];
    const float* W_dec    = (const float*)d_in[6];
    const float* b_dec    = (const float*)d_in[7];
    const float* W_att    = (const float*)d_in[8];
    const float* b_att    = (const float*)d_in[9];
    const float* conv_w   = (const float*)d_in[10];
    const float* gvec     = (const float*)d_in[11];
    const float* W_o      = (const float*)d_in[12];
    const float* b_o      = (const float*)d_in[13];

    float* out = (float*)d_out;
    float* c_dst    = out;
    float* attn_dst = out;
    int write_c = 0, write_attn = 0;
    if (out_size >= NB*OD + NB*NT) {
        c_dst = out; attn_dst = out + NB*OD;
        write_c = 1; write_attn = 1;
    } else if (out_size == NB*NT) {
        attn_dst = out; write_attn = 1;
    } else {
        c_dst = out; write_c = 1;
    }

    static int smem_set = 0;
    if (!smem_set) {
        cudaFuncSetAttribute(gemm_e_mma, cudaFuncAttributeMaxDynamicSharedMemorySize, DYN_SMEM);
        smem_set = 1;
    }

    btrans_kernel<<<dim3(KEXT/32, AD/32), dim3(32,32)>>>(W_enc, W_att);
    conv_kernel<<<dim3(8, NB), 256>>>(att_prev, conv_w);
    bias_kernel<<<NB, AD>>>(dec_h, W_dec, b_dec, b_enc, b_att);
    zero_kernel<<<(MROWS + 255)/256, 256>>>();
    gemm_e_mma<<<dim3(4, 500), 256, DYN_SMEM>>>(enc_pad, gvec);
    softmax_kernel<<<NB, 256>>>(enc_len, attn_dst, write_attn);
    ctx_kernel<<<dim3(NB, 8), 256>>>(enc_pad);
    out_kernel<<<NB, 256>>>(W_o, b_o, c_dst, write_c);
}

// round 5
// speedup vs baseline: 2.3740x; 1.0611x over previous
#include <cuda_runtime.h>
#include <cstdint>
#include <math.h>

#define NB 32
#define NT 2000
#define ED 1024
#define AD 512
#define CCH 32
#define KHALF 50
#define KW 101
#define OD 1024
#define MROWS (NB*NT)     /* 64000 */
#define KEXT (ED + CCH)   /* 1056 */

// ---------------- device scratch (allocation-free) ----------------
__device__ __align__(128) float g_Bt[AD * KEXT];      // [n][k], tf32-rounded
__device__ __align__(128) float g_convT[MROWS * CCH]; // [row][c]
__device__ float g_bias[NB * AD];
__device__ float g_e4[4 * MROWS];                     // per-Nblock partial e
__device__ float g_attn[MROWS];
__device__ float g_ctx[NB * ED];

// ---------------- helpers ----------------
__device__ __forceinline__ void cp16(uint32_t dst, const void* src) {
    asm volatile("cp.async.cg.shared.global [%0], [%1], 16;" :: "r"(dst), "l"(src) : "memory");
}
__device__ __forceinline__ uint32_t smem_u32(const void* p) {
    uint32_t a;
    asm("{ .reg .u64 t; cvta.to.shared.u64 t, %1; cvt.u32.u64 %0, t; }" : "=r"(a) : "l"(p));
    return a;
}
__device__ __forceinline__ float tf32_rna_f(float f) {
    uint32_t u; asm("cvt.rna.tf32.f32 %0, %1;" : "=r"(u) : "f"(f));
    return __uint_as_float(u);
}
__device__ __forceinline__ float fast_tanh(float x) {
    float y; asm("tanh.approx.f32 %0, %1;" : "=f"(y) : "f"(x)); return y;
}
__device__ __forceinline__ void ldmx4(uint32_t& r0, uint32_t& r1, uint32_t& r2, uint32_t& r3,
                                      uint32_t addr) {
    asm volatile("ldmatrix.sync.aligned.m8n8.x4.shared.b16 {%0,%1,%2,%3}, [%4];"
                 : "=r"(r0), "=r"(r1), "=r"(r2), "=r"(r3) : "r"(addr));
}
__device__ __forceinline__ void mma_tf32(float& d0, float& d1, float& d2, float& d3,
                                         uint32_t a0, uint32_t a1, uint32_t a2, uint32_t a3,
                                         uint32_t b0, uint32_t b1) {
    asm volatile(
        "mma.sync.aligned.m16n8k8.row.col.f32.tf32.tf32.f32 "
        "{%0,%1,%2,%3},{%4,%5,%6,%7},{%8,%9},{%0,%1,%2,%3};"
        : "+f"(d0), "+f"(d1), "+f"(d2), "+f"(d3)
        : "r"(a0), "r"(a1), "r"(a2), "r"(a3), "r"(b0), "r"(b1));
}

// ---------------------------------------------------------------------------
// Pack B' = [W_enc ; W_att] transposed K-major, pre-rounded to tf32 (RNA)
// ---------------------------------------------------------------------------
__global__ void btrans_kernel(const float* __restrict__ W_enc,
                              const float* __restrict__ W_att) {
    __shared__ float sm[32][33];
    int tx = threadIdx.x, ty = threadIdx.y;
    int k = blockIdx.x * 32 + ty;
    int n = blockIdx.y * 32 + tx;
    sm[ty][tx] = (k < ED) ? W_enc[k * AD + n] : W_att[(k - ED) * AD + n];
    __syncthreads();
    g_Bt[(blockIdx.y * 32 + ty) * KEXT + blockIdx.x * 32 + tx] = tf32_rna_f(sm[tx][ty]);
}

// ---------------------------------------------------------------------------
// Location conv -> row-major channels: g_convT[(b*NT+t)*32 + c]
// ---------------------------------------------------------------------------
__global__ void conv_kernel(const float* __restrict__ att_prev,
                            const float* __restrict__ conv_w) {
    __shared__ float ap[350];
    __shared__ float wk[CCH * KW];
    int b = blockIdx.y;
    int t0 = blockIdx.x * 250;
    for (int i = threadIdx.x; i < 350; i += 256) {
        int gidx = t0 - KHALF + i;
        ap[i] = (gidx >= 0 && gidx < NT) ? att_prev[b * NT + gidx] : 0.f;
    }
    for (int i = threadIdx.x; i < CCH * KW; i += 256) wk[i] = conv_w[i];
    __syncthreads();
    int lt = threadIdx.x;
    if (lt < 250) {
        float s[CCH];
        #pragma unroll
        for (int c = 0; c < CCH; c++) s[c] = 0.f;
        for (int k = 0; k < KW; k++) {
            float av = ap[lt + k];
            #pragma unroll
            for (int c = 0; c < CCH; c++) s[c] = fmaf(av, wk[c * KW + k], s[c]);
        }
        float4* dst = reinterpret_cast<float4*>(&g_convT[(size_t)(b * NT + t0 + lt) * CCH]);
        #pragma unroll
        for (int q = 0; q < 8; q++) dst[q] = make_float4(s[4*q], s[4*q+1], s[4*q+2], s[4*q+3]);
    }
}

// ---------------------------------------------------------------------------
// bias[b,a] = dec_h[b]@W_dec + b_dec + b_enc + b_att
// ---------------------------------------------------------------------------
__global__ void bias_kernel(const float* __restrict__ dec_h,
                            const float* __restrict__ W_dec,
                            const float* __restrict__ b_dec,
                            const float* __restrict__ b_enc,
                            const float* __restrict__ b_att) {
    __shared__ float ds[ED];
    int b = blockIdx.x;
    for (int d = threadIdx.x; d < ED; d += blockDim.x) ds[d] = dec_h[b*ED + d];
    __syncthreads();
    int a = threadIdx.x;
    float acc = b_dec[a] + b_enc[a] + b_att[a];
    #pragma unroll 8
    for (int d = 0; d < ED; d++) acc = fmaf(ds[d], W_dec[d*AD + a], acc);
    g_bias[b*AD + a] = acc;
}

__global__ void zero_ctx_kernel() {
    int i = blockIdx.x * 256 + threadIdx.x;
    if (i < NB*ED) g_ctx[i] = 0.f;
}

// ---------------------------------------------------------------------------
// Main GEMM (mma.sync tf32 + ldmatrix): e4 = reduce_n tanh(A'@B' + bias)*g
// M=64000, N=512 (4 n-blocks of 128), K'=1056 (33 tiles of 32).
// CTA 128x128, 8 warps (2m x 4n), warp 64x32. 3-stage cp.async, 1 sync/tile.
// A operands: raw fp32 bits (HMMA tf32 reads high 19 bits; RZ truncation).
// ---------------------------------------------------------------------------
#define STAGE_B 36864          /* A 18432 + B 18432; rows of 144B (36 fl) */
#define DYN_SMEM (3*STAGE_B)

__global__ __launch_bounds__(256)
void gemm_e_mma(const float* __restrict__ enc, const float* __restrict__ gv) {
    extern __shared__ char dyn[];
    __shared__ float gS[128];
    __shared__ float biasS[2][128];
    __shared__ float e_buf[4][128];

    const int tid = threadIdx.x, lane = tid & 31, wid = tid >> 5;
    const int wm = wid >> 2, wn = wid & 3;
    const int g = lane >> 2, c4 = lane & 3;
    const int n0 = blockIdx.x * 128;
    const int m0 = blockIdx.y * 128;
    const uint32_t sbase = smem_u32(dyn);
    const int bA = m0 / NT, bB = (m0 + 127) / NT;

    if (tid < 128) {
        gS[tid] = gv[n0 + tid];
        biasS[0][tid] = g_bias[bA*AD + n0 + tid];
    } else {
        biasS[1][tid-128] = g_bias[bB*AD + n0 + tid - 128];
    }

    // per-lane ldmatrix base offsets (bytes)
    const int j8 = lane & 7, q = lane >> 3;
    const uint32_t aOff = (uint32_t)((wm*64 + j8 + (q & 1)*8) * 144 + ((q >> 1) & 1)*16);
    const uint32_t bOff = (uint32_t)((wn*32 + j8 + ((q >> 1) & 1)*8) * 144 + (q & 1)*16) + 18432u;
    uint32_t aAddr[3], bAddr[3];
    #pragma unroll
    for (int s = 0; s < 3; s++) {
        aAddr[s] = sbase + s*STAGE_B + aOff;
        bAddr[s] = sbase + s*STAGE_B + bOff;
    }

    float d[4][4][4];
    #pragma unroll
    for (int i = 0; i < 4; i++)
        #pragma unroll
        for (int jx = 0; jx < 4; jx++)
            #pragma unroll
            for (int qx = 0; qx < 4; qx++) d[i][jx][qx] = 0.f;

    auto issue_tile = [&](int i, int s) {
        uint32_t stA = sbase + s * STAGE_B;
        uint32_t stB = stA + 18432;
        #pragma unroll
        for (int qq = 0; qq < 4; qq++) {
            int u = qq * 256 + tid;
            int row = u >> 3, c16 = u & 7;
            const float* srcA = (i < 32)
                ? enc + (size_t)(m0 + row) * ED + i * 32 + c16 * 4
                : g_convT + (size_t)(m0 + row) * CCH + c16 * 4;
            cp16(stA + row * 144 + c16 * 16, srcA);
            const float* srcB = g_Bt + (size_t)(n0 + row) * KEXT + i * 32 + c16 * 4;
            cp16(stB + row * 144 + c16 * 16, srcB);
        }
        asm volatile("cp.async.commit_group;" ::: "memory");
    };

    issue_tile(0, 0);
    issue_tile(1, 1);

    int st = 0;
    for (int i = 0; i < 33; i++) {
        if (i < 32) asm volatile("cp.async.wait_group 1;" ::: "memory");
        else        asm volatile("cp.async.wait_group 0;" ::: "memory");
        __syncthreads();
        if (i + 2 <= 32) {
            int s2 = st + 2; if (s2 >= 3) s2 -= 3;
            issue_tile(i + 2, s2);
        }

        const uint32_t aS = aAddr[st], bS = bAddr[st];
        #pragma unroll
        for (int ks = 0; ks < 4; ks++) {
            uint32_t br[4][2];
            #pragma unroll
            for (int nfp = 0; nfp < 2; nfp++)
                ldmx4(br[2*nfp][0], br[2*nfp][1], br[2*nfp+1][0], br[2*nfp+1][1],
                      bS + nfp*2304 + ks*32);
            #pragma unroll
            for (int mf = 0; mf < 4; mf++) {
                uint32_t a0, a1, a2, a3;
                ldmx4(a0, a1, a2, a3, aS + mf*2304 + ks*32);
                #pragma unroll
                for (int nf = 0; nf < 4; nf++)
                    mma_tf32(d[mf][nf][0], d[mf][nf][1], d[mf][nf][2], d[mf][nf][3],
                             a0, a1, a2, a3, br[nf][0], br[nf][1]);
            }
        }
        if (++st == 3) st = 0;
    }

    // ---- epilogue: tanh + g-dot, reduce to e-partial ----
    float pr[4][2];
    #pragma unroll
    for (int mf = 0; mf < 4; mf++) { pr[mf][0] = 0.f; pr[mf][1] = 0.f; }

    #pragma unroll
    for (int mf = 0; mf < 4; mf++) {
        int r_lo = wm * 64 + mf * 16 + g;
        int bi_lo = ((m0 + r_lo) / NT == bA) ? 0 : 1;
        int bi_hi = ((m0 + r_lo + 8) / NT == bA) ? 0 : 1;
        #pragma unroll
        for (int nf = 0; nf < 4; nf++) {
            #pragma unroll
            for (int jx = 0; jx < 4; jx++) {
                int colL = wn * 32 + nf * 8 + 2 * c4 + (jx & 1);
                int bi = (jx >= 2) ? bi_hi : bi_lo;
                float v = d[mf][nf][jx] + biasS[bi][colL];
                pr[mf][jx >= 2] = fmaf(fast_tanh(v), gS[colL], pr[mf][jx >= 2]);
            }
        }
    }
    #pragma unroll
    for (int mf = 0; mf < 4; mf++) {
        #pragma unroll
        for (int h = 0; h < 2; h++) {
            pr[mf][h] += __shfl_xor_sync(0xffffffffu, pr[mf][h], 1);
            pr[mf][h] += __shfl_xor_sync(0xffffffffu, pr[mf][h], 2);
        }
    }
    if (c4 == 0) {
        #pragma unroll
        for (int mf = 0; mf < 4; mf++) {
            e_buf[wn][wm * 64 + mf * 16 + g]     = pr[mf][0];
            e_buf[wn][wm * 64 + mf * 16 + g + 8] = pr[mf][1];
        }
    }
    __syncthreads();
    if (tid < 128)
        g_e4[blockIdx.x * MROWS + m0 + tid] =
            (e_buf[0][tid] + e_buf[1][tid]) + (e_buf[2][tid] + e_buf[3][tid]);
}

// ---------------------------------------------------------------------------
// Masked softmax (SCALING=2) over summed e-partials
// ---------------------------------------------------------------------------
__global__ void softmax_kernel(const int* __restrict__ enc_len,
                               float* __restrict__ attn_dst, int write_dst) {
    __shared__ float red[256];
    __shared__ float eS[NT];
    int b = blockIdx.x;
    int len = enc_len[b];

    for (int t = threadIdx.x; t < NT; t += 256) {
        int r = b * NT + t;
        eS[t] = (g_e4[r] + g_e4[MROWS + r]) + (g_e4[2*MROWS + r] + g_e4[3*MROWS + r]);
    }
    __syncthreads();

    float m = -1e30f;
    for (int t = threadIdx.x; t < NT; t += 256)
        if (t < len) m = fmaxf(m, 2.f * eS[t]);
    red[threadIdx.x] = m; __syncthreads();
    for (int s = 128; s > 0; s >>= 1) {
        if (threadIdx.x < s) red[threadIdx.x] = fmaxf(red[threadIdx.x], red[threadIdx.x+s]);
        __syncthreads();
    }
    m = red[0]; __syncthreads();

    float sum = 0.f;
    for (int t = threadIdx.x; t < NT; t += 256)
        if (t < len) sum += expf(2.f * eS[t] - m);
    red[threadIdx.x] = sum; __syncthreads();
    for (int s = 128; s > 0; s >>= 1) {
        if (threadIdx.x < s) red[threadIdx.x] += red[threadIdx.x+s];
        __syncthreads();
    }
    float inv = 1.f / red[0];

    for (int t = threadIdx.x; t < NT; t += 256) {
        float v = (t < len) ? expf(2.f * eS[t] - m) * inv : 0.f;
        g_attn[b*NT + t] = v;
        if (write_dst) attn_dst[b*NT + t] = v;
    }
}

// ---------------------------------------------------------------------------
// ctx[b,d] = sum_t attn[b,t] * enc[b,t,d]
// ---------------------------------------------------------------------------
__global__ void ctx_kernel(const float* __restrict__ enc) {
    int b = blockIdx.x;
    int t0 = blockIdx.y * 250, t1 = t0 + 250;
    float acc[4] = {0.f, 0.f, 0.f, 0.f};
    for (int t = t0; t < t1; t++) {
        float w = g_attn[b*NT + t];
        if (w != 0.f) {
            const float* row = &enc[((size_t)b*NT + t)*ED];
            #pragma unroll
            for (int q = 0; q < 4; q++)
                acc[q] = fmaf(w, row[threadIdx.x + q*256], acc[q]);
        }
    }
    #pragma unroll
    for (int q = 0; q < 4; q++)
        atomicAdd(&g_ctx[b*ED + threadIdx.x + q*256], acc[q]);
}

// ---------------------------------------------------------------------------
// c[b,o] = ctx[b]@W_o + b_o
// ---------------------------------------------------------------------------
__global__ void out_kernel(const float* __restrict__ W_o,
                           const float* __restrict__ b_o,
                           float* __restrict__ c_dst, int write_dst) {
    __shared__ float cs[ED];
    int b = blockIdx.x;
    for (int d = threadIdx.x; d < ED; d += 256) cs[d] = g_ctx[b*ED + d];
    __syncthreads();
    if (!write_dst) return;
    float acc[4];
    #pragma unroll
    for (int q = 0; q < 4; q++) acc[q] = b_o[threadIdx.x + q*256];
    for (int d = 0; d < ED; d++) {
        float cv = cs[d];
        #pragma unroll
        for (int q = 0; q < 4; q++)
            acc[q] = fmaf(cv, W_o[d*OD + threadIdx.x + q*256], acc[q]);
    }
    #pragma unroll
    for (int q = 0; q < 4; q++)
        c_dst[b*OD + threadIdx.x + q*256] = acc[q];
}

// ---------------------------------------------------------------------------
extern "C" void kernel_launch(void* const* d_in, const int* in_sizes, int n_in,
                              void* d_out, int out_size) {
    const float* enc_pad  = (const float*)d_in[0];
    const int*   enc_len  = (const int*)  d_in[1];
    const float* dec_h    = (const float*)d_in[2];
    const float* att_prev = (const float*)d_in[3];
    const float* W_enc    = (const float*)d_in[4];
    const float* b_enc    = (const float*)d_in[5];
    const float* W_dec    = (const float*)d_in[6];
    const float* b_dec    = (const float*)d_in[7];
    const float* W_att    = (const float*)d_in[8];
    const float* b_att    = (const float*)d_in[9];
    const float* conv_w   = (const float*)d_in[10];
    const float* gvec     = (const float*)d_in[11];
    const float* W_o      = (const float*)d_in[12];
    const float* b_o      = (const float*)d_in[13];

    float* out = (float*)d_out;
    float* c_dst    = out;
    float* attn_dst = out;
    int write_c = 0, write_attn = 0;
    if (out_size >= NB*OD + NB*NT) {
        c_dst = out; attn_dst = out + NB*OD;
        write_c = 1; write_attn = 1;
    } else if (out_size == NB*NT) {
        attn_dst = out; write_attn = 1;
    } else {
        c_dst = out; write_c = 1;
    }

    static int smem_set = 0;
    if (!smem_set) {
        cudaFuncSetAttribute(gemm_e_mma, cudaFuncAttributeMaxDynamicSharedMemorySize, DYN_SMEM);
        smem_set = 1;
    }

    btrans_kernel<<<dim3(KEXT/32, AD/32), dim3(32,32)>>>(W_enc, W_att);
    conv_kernel<<<dim3(8, NB), 256>>>(att_prev, conv_w);
    bias_kernel<<<NB, AD>>>(dec_h, W_dec, b_dec, b_enc, b_att);
    zero_ctx_kernel<<<(NB*ED + 255)/256, 256>>>();
    gemm_e_mma<<<dim3(4, 500), 256, DYN_SMEM>>>(enc_pad, gvec);
    softmax_kernel<<<NB, 256>>>(enc_len, attn_dst, write_attn);
    ctx_kernel<<<dim3(NB, 8), 256>>>(enc_pad);
    out_kernel<<<NB, 256>>>(W_o, b_o, c_dst, write_c);
}

// round 6
// speedup vs baseline: 3.2738x; 1.3790x over previous
#include <cuda_runtime.h>
#include <cuda_fp16.h>
#include <cstdint>
#include <math.h>

#define NB 32
#define NT 2000
#define ED 1024
#define AD 512
#define CCH 32
#define KHALF 50
#define KW 101
#define OD 1024
#define MROWS (NB*NT)     /* 64000 */
#define KEXT (ED + CCH)   /* 1056 */

// ---------------- device scratch (allocation-free) ----------------
__device__ __align__(128) __half g_Ah[(size_t)MROWS * KEXT];  // enc || conv, fp16 (135MB)
__device__ __align__(128) __half g_Bth[AD * KEXT];            // [n][k] fp16
__device__ float g_bias[NB * AD];
__device__ float g_e4[4 * MROWS];                             // per-Nblock partial e
__device__ float g_attn[MROWS];
__device__ float g_ctx[NB * ED];

// ---------------- helpers ----------------
__device__ __forceinline__ void cp16(uint32_t dst, const void* src) {
    asm volatile("cp.async.cg.shared.global [%0], [%1], 16;" :: "r"(dst), "l"(src) : "memory");
}
__device__ __forceinline__ uint32_t smem_u32(const void* p) {
    uint32_t a;
    asm("{ .reg .u64 t; cvta.to.shared.u64 t, %1; cvt.u32.u64 %0, t; }" : "=r"(a) : "l"(p));
    return a;
}
__device__ __forceinline__ uint32_t h2u(__half2 h) {
    return *reinterpret_cast<uint32_t*>(&h);
}
__device__ __forceinline__ float fast_tanh(float x) {
    float y; asm("tanh.approx.f32 %0, %1;" : "=f"(y) : "f"(x)); return y;
}
__device__ __forceinline__ void ldmx4(uint32_t& r0, uint32_t& r1, uint32_t& r2, uint32_t& r3,
                                      uint32_t addr) {
    asm volatile("ldmatrix.sync.aligned.m8n8.x4.shared.b16 {%0,%1,%2,%3}, [%4];"
                 : "=r"(r0), "=r"(r1), "=r"(r2), "=r"(r3) : "r"(addr));
}
__device__ __forceinline__ void mma_f16(float& d0, float& d1, float& d2, float& d3,
                                        uint32_t a0, uint32_t a1, uint32_t a2, uint32_t a3,
                                        uint32_t b0, uint32_t b1) {
    asm volatile(
        "mma.sync.aligned.m16n8k16.row.col.f32.f16.f16.f32 "
        "{%0,%1,%2,%3},{%4,%5,%6,%7},{%8,%9},{%0,%1,%2,%3};"
        : "+f"(d0), "+f"(d1), "+f"(d2), "+f"(d3)
        : "r"(a0), "r"(a1), "r"(a2), "r"(a3), "r"(b0), "r"(b1));
}

// ---------------------------------------------------------------------------
// prep_A: blocks 0..1999 convert enc rows to fp16 (cols 0..1023 of g_Ah);
//         blocks 2000..2255 compute location conv -> fp16 (cols 1024..1055).
// ---------------------------------------------------------------------------
__global__ void prep_A(const float* __restrict__ enc,
                       const float* __restrict__ att_prev,
                       const float* __restrict__ conv_w) {
    __shared__ float ap[350];
    __shared__ float wk[CCH * KW];
    const int tid = threadIdx.x;
    if (blockIdx.x < 2000) {
        const int r0 = blockIdx.x * 32;
        #pragma unroll 4
        for (int q = 0; q < 32; q++) {
            int u = q * 256 + tid;           // 0..8191 float4 units
            int row = u >> 8, c4 = u & 255;
            float4 v = *reinterpret_cast<const float4*>(enc + (size_t)(r0 + row) * ED + c4 * 4);
            uint2 pk = make_uint2(h2u(__floats2half2_rn(v.x, v.y)),
                                  h2u(__floats2half2_rn(v.z, v.w)));
            *reinterpret_cast<uint2*>(g_Ah + (size_t)(r0 + row) * KEXT + c4 * 4) = pk;
        }
    } else {
        int idx = blockIdx.x - 2000;
        int b = idx >> 3;
        int t0 = (idx & 7) * 250;
        for (int i = tid; i < 350; i += 256) {
            int gpos = t0 - KHALF + i;
            ap[i] = (gpos >= 0 && gpos < NT) ? att_prev[b * NT + gpos] : 0.f;
        }
        for (int i = tid; i < CCH * KW; i += 256) wk[i] = conv_w[i];
        __syncthreads();
        if (tid < 250) {
            float s[CCH];
            #pragma unroll
            for (int c = 0; c < CCH; c++) s[c] = 0.f;
            for (int k = 0; k < KW; k++) {
                float av = ap[tid + k];
                #pragma unroll
                for (int c = 0; c < CCH; c++) s[c] = fmaf(av, wk[c * KW + k], s[c]);
            }
            uint32_t u32[16];
            #pragma unroll
            for (int k = 0; k < 16; k++) u32[k] = h2u(__floats2half2_rn(s[2*k], s[2*k+1]));
            uint4* dst = reinterpret_cast<uint4*>(g_Ah + (size_t)(b * NT + t0 + tid) * KEXT + ED);
            dst[0] = make_uint4(u32[0], u32[1], u32[2], u32[3]);
            dst[1] = make_uint4(u32[4], u32[5], u32[6], u32[7]);
            dst[2] = make_uint4(u32[8], u32[9], u32[10], u32[11]);
            dst[3] = make_uint4(u32[12], u32[13], u32[14], u32[15]);
        }
    }
}

// ---------------------------------------------------------------------------
// B' = [W_enc ; W_att] transposed K-major -> fp16 g_Bth[n][k]
// ---------------------------------------------------------------------------
__global__ void btrans_kernel(const float* __restrict__ W_enc,
                              const float* __restrict__ W_att) {
    __shared__ float sm[32][33];
    int tx = threadIdx.x, ty = threadIdx.y;
    int k = blockIdx.x * 32 + ty;
    int n = blockIdx.y * 32 + tx;
    sm[ty][tx] = (k < ED) ? W_enc[k * AD + n] : W_att[(k - ED) * AD + n];
    __syncthreads();
    g_Bth[(blockIdx.y * 32 + ty) * KEXT + blockIdx.x * 32 + tx] = __float2half_rn(sm[tx][ty]);
}

// ---------------------------------------------------------------------------
// bias[b,a] = dec_h[b]@W_dec + b_dec + b_enc + b_att   (grid 32 x 2)
// ---------------------------------------------------------------------------
__global__ void bias_kernel(const float* __restrict__ dec_h,
                            const float* __restrict__ W_dec,
                            const float* __restrict__ b_dec,
                            const float* __restrict__ b_enc,
                            const float* __restrict__ b_att) {
    __shared__ float ds[ED];
    int b = blockIdx.x;
    int a = blockIdx.y * 256 + threadIdx.x;
    for (int d = threadIdx.x; d < ED; d += 256) ds[d] = dec_h[b*ED + d];
    __syncthreads();
    float acc = b_dec[a] + b_enc[a] + b_att[a];
    #pragma unroll 8
    for (int d = 0; d < ED; d++) acc = fmaf(ds[d], W_dec[d*AD + a], acc);
    g_bias[b*AD + a] = acc;
}

// ---------------------------------------------------------------------------
// Main GEMM (mma.sync fp16 m16n8k16 + ldmatrix).
// M=64000, N=512 (4 n-blocks), K'=1056 (33 tiles of 32).
// CTA 128x128, 8 warps (2m x 4n); 3-stage cp.async; rows padded to 80B.
// ---------------------------------------------------------------------------
#define PITCH 80
#define STAGE 20480            /* A 10240 + B 10240 */
#define DYN_SMEM (3*STAGE)

__global__ __launch_bounds__(256, 2)
void gemm_e_mma(const float* __restrict__ gv) {
    extern __shared__ char dyn[];
    __shared__ float gS[128];
    __shared__ float biasS[2][128];
    __shared__ float e_buf[4][128];

    const int tid = threadIdx.x, lane = tid & 31, wid = tid >> 5;
    const int wm = wid >> 2, wn = wid & 3;
    const int g = lane >> 2, c4 = lane & 3;
    const int n0 = blockIdx.x * 128;
    const int m0 = blockIdx.y * 128;
    const uint32_t sbase = smem_u32(dyn);
    const int bA = m0 / NT, bB = (m0 + 127) / NT;

    if (tid < 128) {
        gS[tid] = gv[n0 + tid];
        biasS[0][tid] = g_bias[bA*AD + n0 + tid];
    } else {
        biasS[1][tid-128] = g_bias[bB*AD + n0 + tid - 128];
    }

    // per-lane ldmatrix offsets (bytes)
    const uint32_t aOff = (uint32_t)((wm*64 + (lane & 15)) * PITCH + ((lane >> 4) & 1) * 16);
    const uint32_t bOff = 10240u +
        (uint32_t)((wn*32 + (lane & 7) + ((lane >> 4) & 1) * 8) * PITCH + ((lane >> 3) & 1) * 16);
    uint32_t aAddr[3], bAddr[3];
    #pragma unroll
    for (int s = 0; s < 3; s++) {
        aAddr[s] = sbase + s*STAGE + aOff;
        bAddr[s] = sbase + s*STAGE + bOff;
    }

    float d[4][4][4];
    #pragma unroll
    for (int i = 0; i < 4; i++)
        #pragma unroll
        for (int jx = 0; jx < 4; jx++)
            #pragma unroll
            for (int qx = 0; qx < 4; qx++) d[i][jx][qx] = 0.f;

    auto issue_tile = [&](int i, int s) {
        uint32_t stA = sbase + s * STAGE;
        uint32_t stB = stA + 10240;
        #pragma unroll
        for (int q = 0; q < 2; q++) {
            int u = q * 256 + tid;           // 0..511
            int row = u >> 2, c16 = u & 3;
            cp16(stA + row * PITCH + c16 * 16,
                 g_Ah + (size_t)(m0 + row) * KEXT + i * 32 + c16 * 8);
            cp16(stB + row * PITCH + c16 * 16,
                 g_Bth + (size_t)(n0 + row) * KEXT + i * 32 + c16 * 8);
        }
        asm volatile("cp.async.commit_group;" ::: "memory");
    };

    issue_tile(0, 0);
    issue_tile(1, 1);

    int st = 0;
    for (int i = 0; i < 33; i++) {
        if (i < 32) asm volatile("cp.async.wait_group 1;" ::: "memory");
        else        asm volatile("cp.async.wait_group 0;" ::: "memory");
        __syncthreads();
        if (i + 2 <= 32) {
            int s2 = st + 2; if (s2 >= 3) s2 -= 3;
            issue_tile(i + 2, s2);
        }

        const uint32_t aS = aAddr[st], bS = bAddr[st];
        #pragma unroll
        for (int ks = 0; ks < 2; ks++) {
            uint32_t br[4][2];
            ldmx4(br[0][0], br[0][1], br[1][0], br[1][1], bS + ks*32);
            ldmx4(br[2][0], br[2][1], br[3][0], br[3][1], bS + 16*PITCH + ks*32);
            #pragma unroll
            for (int mf = 0; mf < 4; mf++) {
                uint32_t a0, a1, a2, a3;
                ldmx4(a0, a1, a2, a3, aS + mf*16*PITCH + ks*32);
                #pragma unroll
                for (int nf = 0; nf < 4; nf++)
                    mma_f16(d[mf][nf][0], d[mf][nf][1], d[mf][nf][2], d[mf][nf][3],
                            a0, a1, a2, a3, br[nf][0], br[nf][1]);
            }
        }
        if (++st == 3) st = 0;
    }

    // ---- epilogue: tanh + g-dot, reduce to e-partial ----
    float pr[4][2];
    #pragma unroll
    for (int mf = 0; mf < 4; mf++) { pr[mf][0] = 0.f; pr[mf][1] = 0.f; }

    #pragma unroll
    for (int mf = 0; mf < 4; mf++) {
        int r_lo = wm * 64 + mf * 16 + g;
        int bi_lo = ((m0 + r_lo) / NT == bA) ? 0 : 1;
        int bi_hi = ((m0 + r_lo + 8) / NT == bA) ? 0 : 1;
        #pragma unroll
        for (int nf = 0; nf < 4; nf++) {
            #pragma unroll
            for (int jx = 0; jx < 4; jx++) {
                int colL = wn * 32 + nf * 8 + 2 * c4 + (jx & 1);
                int bi = (jx >= 2) ? bi_hi : bi_lo;
                float v = d[mf][nf][jx] + biasS[bi][colL];
                pr[mf][jx >= 2] = fmaf(fast_tanh(v), gS[colL], pr[mf][jx >= 2]);
            }
        }
    }
    #pragma unroll
    for (int mf = 0; mf < 4; mf++) {
        #pragma unroll
        for (int h = 0; h < 2; h++) {
            pr[mf][h] += __shfl_xor_sync(0xffffffffu, pr[mf][h], 1);
            pr[mf][h] += __shfl_xor_sync(0xffffffffu, pr[mf][h], 2);
        }
    }
    if (c4 == 0) {
        #pragma unroll
        for (int mf = 0; mf < 4; mf++) {
            e_buf[wn][wm * 64 + mf * 16 + g]     = pr[mf][0];
            e_buf[wn][wm * 64 + mf * 16 + g + 8] = pr[mf][1];
        }
    }
    __syncthreads();
    if (tid < 128)
        g_e4[blockIdx.x * MROWS + m0 + tid] =
            (e_buf[0][tid] + e_buf[1][tid]) + (e_buf[2][tid] + e_buf[3][tid]);
}

// ---------------------------------------------------------------------------
// Masked softmax (SCALING=2) over summed partials; also zeroes g_ctx[b].
// ---------------------------------------------------------------------------
__global__ void softmax_kernel(const int* __restrict__ enc_len,
                               float* __restrict__ attn_dst, int write_dst) {
    __shared__ float red[256];
    __shared__ float eS[NT];
    int b = blockIdx.x;
    int len = enc_len[b];

    for (int d = threadIdx.x; d < ED; d += 256) g_ctx[b*ED + d] = 0.f;
    for (int t = threadIdx.x; t < NT; t += 256) {
        int r = b * NT + t;
        eS[t] = (g_e4[r] + g_e4[MROWS + r]) + (g_e4[2*MROWS + r] + g_e4[3*MROWS + r]);
    }
    __syncthreads();

    float m = -1e30f;
    for (int t = threadIdx.x; t < NT; t += 256)
        if (t < len) m = fmaxf(m, 2.f * eS[t]);
    red[threadIdx.x] = m; __syncthreads();
    for (int s = 128; s > 0; s >>= 1) {
        if (threadIdx.x < s) red[threadIdx.x] = fmaxf(red[threadIdx.x], red[threadIdx.x+s]);
        __syncthreads();
    }
    m = red[0]; __syncthreads();

    float sum = 0.f;
    for (int t = threadIdx.x; t < NT; t += 256)
        if (t < len) sum += expf(2.f * eS[t] - m);
    red[threadIdx.x] = sum; __syncthreads();
    for (int s = 128; s > 0; s >>= 1) {
        if (threadIdx.x < s) red[threadIdx.x] += red[threadIdx.x+s];
        __syncthreads();
    }
    float inv = 1.f / red[0];

    for (int t = threadIdx.x; t < NT; t += 256) {
        float v = (t < len) ? expf(2.f * eS[t] - m) * inv : 0.f;
        g_attn[b*NT + t] = v;
        if (write_dst) attn_dst[b*NT + t] = v;
    }
}

// ---------------------------------------------------------------------------
// ctx[b,d] = sum_t attn[b,t] * enc[b,t,d]
// ---------------------------------------------------------------------------
__global__ void ctx_kernel(const float* __restrict__ enc) {
    int b = blockIdx.x;
    int t0 = blockIdx.y * 250, t1 = t0 + 250;
    float acc[4] = {0.f, 0.f, 0.f, 0.f};
    for (int t = t0; t < t1; t++) {
        float w = g_attn[b*NT + t];
        if (w != 0.f) {
            const float* row = &enc[((size_t)b*NT + t)*ED];
            #pragma unroll
            for (int q = 0; q < 4; q++)
                acc[q] = fmaf(w, row[threadIdx.x + q*256], acc[q]);
        }
    }
    #pragma unroll
    for (int q = 0; q < 4; q++)
        atomicAdd(&g_ctx[b*ED + threadIdx.x + q*256], acc[q]);
}

// ---------------------------------------------------------------------------
// c[b,o] = ctx[b]@W_o + b_o   (grid 32 x 4)
// ---------------------------------------------------------------------------
__global__ void out_kernel(const float* __restrict__ W_o,
                           const float* __restrict__ b_o,
                           float* __restrict__ c_dst, int write_dst) {
    __shared__ float cs[ED];
    int b = blockIdx.x;
    int o = blockIdx.y * 256 + threadIdx.x;
    for (int d = threadIdx.x; d < ED; d += 256) cs[d] = g_ctx[b*ED + d];
    __syncthreads();
    if (!write_dst) return;
    float acc = b_o[o];
    #pragma unroll 8
    for (int d = 0; d < ED; d++)
        acc = fmaf(cs[d], W_o[d*OD + o], acc);
    c_dst[b*OD + o] = acc;
}

// ---------------------------------------------------------------------------
extern "C" void kernel_launch(void* const* d_in, const int* in_sizes, int n_in,
                              void* d_out, int out_size) {
    const float* enc_pad  = (const float*)d_in[0];
    const int*   enc_len  = (const int*)  d_in[1];
    const float* dec_h    = (const float*)d_in[2];
    const float* att_prev = (const float*)d_in[3];
    const float* W_enc    = (const float*)d_in[4];
    const float* b_enc    = (const float*)d_in[5];
    const float* W_dec    = (const float*)d_in[6];
    const float* b_dec    = (const float*)d_in[7];
    const float* W_att    = (const float*)d_in[8];
    const float* b_att    = (const float*)d_in[9];
    const float* conv_w   = (const float*)d_in[10];
    const float* gvec     = (const float*)d_in[11];
    const float* W_o      = (const float*)d_in[12];
    const float* b_o      = (const float*)d_in[13];

    float* out = (float*)d_out;
    float* c_dst    = out;
    float* attn_dst = out;
    int write_c = 0, write_attn = 0;
    if (out_size >= NB*OD + NB*NT) {
        c_dst = out; attn_dst = out + NB*OD;
        write_c = 1; write_attn = 1;
    } else if (out_size == NB*NT) {
        attn_dst = out; write_attn = 1;
    } else {
        c_dst = out; write_c = 1;
    }

    static int smem_set = 0;
    if (!smem_set) {
        cudaFuncSetAttribute(gemm_e_mma, cudaFuncAttributeMaxDynamicSharedMemorySize, DYN_SMEM);
        smem_set = 1;
    }

    prep_A<<<2256, 256>>>(enc_pad, att_prev, conv_w);
    btrans_kernel<<<dim3(KEXT/32, AD/32), dim3(32,32)>>>(W_enc, W_att);
    bias_kernel<<<dim3(NB, 2), 256>>>(dec_h, W_dec, b_dec, b_enc, b_att);
    gemm_e_mma<<<dim3(4, 500), 256, DYN_SMEM>>>(gvec);
    softmax_kernel<<<NB, 256>>>(enc_len, attn_dst, write_attn);
    ctx_kernel<<<dim3(NB, 8), 256>>>(enc_pad);
    out_kernel<<<dim3(NB, 4), 256>>>(W_o, b_o, c_dst, write_c);
}

// round 7
// speedup vs baseline: 4.1473x; 1.2668x over previous
#include <cuda_runtime.h>
#include <cuda_fp16.h>
#include <cstdint>
#include <math.h>

#define NB 32
#define NT 2000
#define ED 1024
#define AD 512
#define CCH 32
#define KHALF 50
#define KW 101
#define OD 1024
#define MROWS (NB*NT)     /* 64000 */
#define KEXT (ED + CCH)   /* 1056 */

// ---------------- device scratch (zero-initialized device globals) ----------
__device__ __align__(128) __half g_Ah[(size_t)MROWS * KEXT];  // enc || conv, fp16
__device__ __align__(128) __half g_Bth[AD * KEXT];            // [n][k] fp16
__device__ float g_bias[NB * AD];
__device__ float g_e4[4 * MROWS];                             // per-Nblock partial e
__device__ float g_attn[MROWS];
__device__ float g_ctx[NB * ED];

// ---------------- helpers ----------------
__device__ __forceinline__ void cp16(uint32_t dst, const void* src) {
    asm volatile("cp.async.cg.shared.global [%0], [%1], 16;" :: "r"(dst), "l"(src) : "memory");
}
__device__ __forceinline__ uint32_t smem_u32(const void* p) {
    uint32_t a;
    asm("{ .reg .u64 t; cvta.to.shared.u64 t, %1; cvt.u32.u64 %0, t; }" : "=r"(a) : "l"(p));
    return a;
}
__device__ __forceinline__ uint32_t h2u(__half2 h) {
    return *reinterpret_cast<uint32_t*>(&h);
}
__device__ __forceinline__ float fast_tanh(float x) {
    float y; asm("tanh.approx.f32 %0, %1;" : "=f"(y) : "f"(x)); return y;
}
__device__ __forceinline__ void ldmx4(uint32_t& r0, uint32_t& r1, uint32_t& r2, uint32_t& r3,
                                      uint32_t addr) {
    asm volatile("ldmatrix.sync.aligned.m8n8.x4.shared.b16 {%0,%1,%2,%3}, [%4];"
                 : "=r"(r0), "=r"(r1), "=r"(r2), "=r"(r3) : "r"(addr));
}
__device__ __forceinline__ void mma_f16(float& d0, float& d1, float& d2, float& d3,
                                        uint32_t a0, uint32_t a1, uint32_t a2, uint32_t a3,
                                        uint32_t b0, uint32_t b1) {
    asm volatile(
        "mma.sync.aligned.m16n8k16.row.col.f32.f16.f16.f32 "
        "{%0,%1,%2,%3},{%4,%5,%6,%7},{%8,%9},{%0,%1,%2,%3};"
        : "+f"(d0), "+f"(d1), "+f"(d2), "+f"(d3)
        : "r"(a0), "r"(a1), "r"(a2), "r"(a3), "r"(b0), "r"(b1));
}

// ---------------------------------------------------------------------------
// prep_A: blocks 0..1999 convert enc rows to fp16 (cols 0..1023 of g_Ah);
//         blocks 2000..2255 location conv -> fp16 (cols 1024..1055).
// Blocks entirely in the masked region (t >= enc_len[b]) exit early; those
// g_Ah rows remain 0 (zero-init) and are never consumed.
// ---------------------------------------------------------------------------
__global__ void prep_A(const float* __restrict__ enc,
                       const float* __restrict__ att_prev,
                       const float* __restrict__ conv_w,
                       const int* __restrict__ enc_len) {
    __shared__ float ap[350];
    __shared__ float wk[CCH * KW];
    const int tid = threadIdx.x;
    if (blockIdx.x < 2000) {
        const int r0 = blockIdx.x * 32;
        const int b0 = r0 / NT, b1 = (r0 + 31) / NT;
        if (b0 == b1 && (r0 - b0 * NT) >= enc_len[b0]) return;
        #pragma unroll 4
        for (int q = 0; q < 32; q++) {
            int u = q * 256 + tid;           // 0..8191 float4 units
            int row = u >> 8, c4 = u & 255;
            float4 v = *reinterpret_cast<const float4*>(enc + (size_t)(r0 + row) * ED + c4 * 4);
            uint2 pk = make_uint2(h2u(__floats2half2_rn(v.x, v.y)),
                                  h2u(__floats2half2_rn(v.z, v.w)));
            *reinterpret_cast<uint2*>(g_Ah + (size_t)(r0 + row) * KEXT + c4 * 4) = pk;
        }
    } else {
        int idx = blockIdx.x - 2000;
        int b = idx >> 3;
        int t0 = (idx & 7) * 250;
        if (t0 >= enc_len[b]) return;
        for (int i = tid; i < 350; i += 256) {
            int gpos = t0 - KHALF + i;
            ap[i] = (gpos >= 0 && gpos < NT) ? att_prev[b * NT + gpos] : 0.f;
        }
        for (int i = tid; i < CCH * KW; i += 256) wk[i] = conv_w[i];
        __syncthreads();
        if (tid < 250) {
            float s[CCH];
            #pragma unroll
            for (int c = 0; c < CCH; c++) s[c] = 0.f;
            for (int k = 0; k < KW; k++) {
                float av = ap[tid + k];
                #pragma unroll
                for (int c = 0; c < CCH; c++) s[c] = fmaf(av, wk[c * KW + k], s[c]);
            }
            uint32_t u32[16];
            #pragma unroll
            for (int k = 0; k < 16; k++) u32[k] = h2u(__floats2half2_rn(s[2*k], s[2*k+1]));
            uint4* dst = reinterpret_cast<uint4*>(g_Ah + (size_t)(b * NT + t0 + tid) * KEXT + ED);
            dst[0] = make_uint4(u32[0], u32[1], u32[2], u32[3]);
            dst[1] = make_uint4(u32[4], u32[5], u32[6], u32[7]);
            dst[2] = make_uint4(u32[8], u32[9], u32[10], u32[11]);
            dst[3] = make_uint4(u32[12], u32[13], u32[14], u32[15]);
        }
    }
}

// ---------------------------------------------------------------------------
// B' = [W_enc ; W_att] transposed K-major -> fp16 g_Bth[n][k]
// ---------------------------------------------------------------------------
__global__ void btrans_kernel(const float* __restrict__ W_enc,
                              const float* __restrict__ W_att) {
    __shared__ float sm[32][33];
    int tx = threadIdx.x, ty = threadIdx.y;
    int k = blockIdx.x * 32 + ty;
    int n = blockIdx.y * 32 + tx;
    sm[ty][tx] = (k < ED) ? W_enc[k * AD + n] : W_att[(k - ED) * AD + n];
    __syncthreads();
    g_Bth[(blockIdx.y * 32 + ty) * KEXT + blockIdx.x * 32 + tx] = __float2half_rn(sm[tx][ty]);
}

// ---------------------------------------------------------------------------
// bias[b,a] = dec_h[b]@W_dec + b_dec + b_enc + b_att   (grid 32 x 2)
// ---------------------------------------------------------------------------
__global__ void bias_kernel(const float* __restrict__ dec_h,
                            const float* __restrict__ W_dec,
                            const float* __restrict__ b_dec,
                            const float* __restrict__ b_enc,
                            const float* __restrict__ b_att) {
    __shared__ float ds[ED];
    int b = blockIdx.x;
    int a = blockIdx.y * 256 + threadIdx.x;
    for (int d = threadIdx.x; d < ED; d += 256) ds[d] = dec_h[b*ED + d];
    __syncthreads();
    float acc = b_dec[a] + b_enc[a] + b_att[a];
    #pragma unroll 8
    for (int d = 0; d < ED; d++) acc = fmaf(ds[d], W_dec[d*AD + a], acc);
    g_bias[b*AD + a] = acc;
}

// ---------------------------------------------------------------------------
// Main GEMM (mma.sync fp16 m16n8k16 + ldmatrix), with masked-CTA early exit.
// ---------------------------------------------------------------------------
#define PITCH 80
#define STAGE 20480            /* A 10240 + B 10240 */
#define DYN_SMEM (3*STAGE)

__global__ __launch_bounds__(256, 2)
void gemm_e_mma(const float* __restrict__ gv, const int* __restrict__ enc_len) {
    extern __shared__ char dyn[];
    __shared__ float gS[128];
    __shared__ float biasS[2][128];
    __shared__ float e_buf[4][128];

    const int tid = threadIdx.x, lane = tid & 31, wid = tid >> 5;
    const int wm = wid >> 2, wn = wid & 3;
    const int g = lane >> 2, c4 = lane & 3;
    const int n0 = blockIdx.x * 128;
    const int m0 = blockIdx.y * 128;
    const int bA = m0 / NT, bB = (m0 + 127) / NT;
    if (bA == bB && (m0 - bA * NT) >= __ldg(&enc_len[bA])) return;

    const uint32_t sbase = smem_u32(dyn);

    if (tid < 128) {
        gS[tid] = gv[n0 + tid];
        biasS[0][tid] = g_bias[bA*AD + n0 + tid];
    } else {
        biasS[1][tid-128] = g_bias[bB*AD + n0 + tid - 128];
    }

    const uint32_t aOff = (uint32_t)((wm*64 + (lane & 15)) * PITCH + ((lane >> 4) & 1) * 16);
    const uint32_t bOff = 10240u +
        (uint32_t)((wn*32 + (lane & 7) + ((lane >> 4) & 1) * 8) * PITCH + ((lane >> 3) & 1) * 16);
    uint32_t aAddr[3], bAddr[3];
    #pragma unroll
    for (int s = 0; s < 3; s++) {
        aAddr[s] = sbase + s*STAGE + aOff;
        bAddr[s] = sbase + s*STAGE + bOff;
    }

    float d[4][4][4];
    #pragma unroll
    for (int i = 0; i < 4; i++)
        #pragma unroll
        for (int jx = 0; jx < 4; jx++)
            #pragma unroll
            for (int qx = 0; qx < 4; qx++) d[i][jx][qx] = 0.f;

    auto issue_tile = [&](int i, int s) {
        uint32_t stA = sbase + s * STAGE;
        uint32_t stB = stA + 10240;
        #pragma unroll
        for (int q = 0; q < 2; q++) {
            int u = q * 256 + tid;           // 0..511
            int row = u >> 2, c16 = u & 3;
            cp16(stA + row * PITCH + c16 * 16,
                 g_Ah + (size_t)(m0 + row) * KEXT + i * 32 + c16 * 8);
            cp16(stB + row * PITCH + c16 * 16,
                 g_Bth + (size_t)(n0 + row) * KEXT + i * 32 + c16 * 8);
        }
        asm volatile("cp.async.commit_group;" ::: "memory");
    };

    issue_tile(0, 0);
    issue_tile(1, 1);

    int st = 0;
    for (int i = 0; i < 33; i++) {
        if (i < 32) asm volatile("cp.async.wait_group 1;" ::: "memory");
        else        asm volatile("cp.async.wait_group 0;" ::: "memory");
        __syncthreads();
        if (i + 2 <= 32) {
            int s2 = st + 2; if (s2 >= 3) s2 -= 3;
            issue_tile(i + 2, s2);
        }

        const uint32_t aS = aAddr[st], bS = bAddr[st];
        #pragma unroll
        for (int ks = 0; ks < 2; ks++) {
            uint32_t br[4][2];
            ldmx4(br[0][0], br[0][1], br[1][0], br[1][1], bS + ks*32);
            ldmx4(br[2][0], br[2][1], br[3][0], br[3][1], bS + 16*PITCH + ks*32);
            #pragma unroll
            for (int mf = 0; mf < 4; mf++) {
                uint32_t a0, a1, a2, a3;
                ldmx4(a0, a1, a2, a3, aS + mf*16*PITCH + ks*32);
                #pragma unroll
                for (int nf = 0; nf < 4; nf++)
                    mma_f16(d[mf][nf][0], d[mf][nf][1], d[mf][nf][2], d[mf][nf][3],
                            a0, a1, a2, a3, br[nf][0], br[nf][1]);
            }
        }
        if (++st == 3) st = 0;
    }

    // ---- epilogue: tanh + g-dot, reduce to e-partial ----
    float pr[4][2];
    #pragma unroll
    for (int mf = 0; mf < 4; mf++) { pr[mf][0] = 0.f; pr[mf][1] = 0.f; }

    #pragma unroll
    for (int mf = 0; mf < 4; mf++) {
        int r_lo = wm * 64 + mf * 16 + g;
        int bi_lo = ((m0 + r_lo) / NT == bA) ? 0 : 1;
        int bi_hi = ((m0 + r_lo + 8) / NT == bA) ? 0 : 1;
        #pragma unroll
        for (int nf = 0; nf < 4; nf++) {
            #pragma unroll
            for (int jx = 0; jx < 4; jx++) {
                int colL = wn * 32 + nf * 8 + 2 * c4 + (jx & 1);
                int bi = (jx >= 2) ? bi_hi : bi_lo;
                float v = d[mf][nf][jx] + biasS[bi][colL];
                pr[mf][jx >= 2] = fmaf(fast_tanh(v), gS[colL], pr[mf][jx >= 2]);
            }
        }
    }
    #pragma unroll
    for (int mf = 0; mf < 4; mf++) {
        #pragma unroll
        for (int h = 0; h < 2; h++) {
            pr[mf][h] += __shfl_xor_sync(0xffffffffu, pr[mf][h], 1);
            pr[mf][h] += __shfl_xor_sync(0xffffffffu, pr[mf][h], 2);
        }
    }
    if (c4 == 0) {
        #pragma unroll
        for (int mf = 0; mf < 4; mf++) {
            e_buf[wn][wm * 64 + mf * 16 + g]     = pr[mf][0];
            e_buf[wn][wm * 64 + mf * 16 + g + 8] = pr[mf][1];
        }
    }
    __syncthreads();
    if (tid < 128)
        g_e4[blockIdx.x * MROWS + m0 + tid] =
            (e_buf[0][tid] + e_buf[1][tid]) + (e_buf[2][tid] + e_buf[3][tid]);
}

// ---------------------------------------------------------------------------
// Masked softmax (SCALING=2); also zeroes g_ctx[b].
// ---------------------------------------------------------------------------
__global__ void softmax_kernel(const int* __restrict__ enc_len,
                               float* __restrict__ attn_dst, int write_dst) {
    __shared__ float red[256];
    __shared__ float eS[NT];
    int b = blockIdx.x;
    int len = enc_len[b];

    for (int d = threadIdx.x; d < ED; d += 256) g_ctx[b*ED + d] = 0.f;
    for (int t = threadIdx.x; t < NT; t += 256) {
        int r = b * NT + t;
        eS[t] = (g_e4[r] + g_e4[MROWS + r]) + (g_e4[2*MROWS + r] + g_e4[3*MROWS + r]);
    }
    __syncthreads();

    float m = -1e30f;
    for (int t = threadIdx.x; t < NT; t += 256)
        if (t < len) m = fmaxf(m, 2.f * eS[t]);
    red[threadIdx.x] = m; __syncthreads();
    for (int s = 128; s > 0; s >>= 1) {
        if (threadIdx.x < s) red[threadIdx.x] = fmaxf(red[threadIdx.x], red[threadIdx.x+s]);
        __syncthreads();
    }
    m = red[0]; __syncthreads();

    float sum = 0.f;
    for (int t = threadIdx.x; t < NT; t += 256)
        if (t < len) sum += expf(2.f * eS[t] - m);
    red[threadIdx.x] = sum; __syncthreads();
    for (int s = 128; s > 0; s >>= 1) {
        if (threadIdx.x < s) red[threadIdx.x] += red[threadIdx.x+s];
        __syncthreads();
    }
    float inv = 1.f / red[0];

    for (int t = threadIdx.x; t < NT; t += 256) {
        float v = (t < len) ? expf(2.f * eS[t] - m) * inv : 0.f;
        g_attn[b*NT + t] = v;
        if (write_dst) attn_dst[b*NT + t] = v;
    }
}

// ---------------------------------------------------------------------------
// ctx[b,d] = sum_t attn[b,t] * enc_fp16[b,t,d]  (reads g_Ah; masked rows are
// exact zeros in both attn and g_Ah). grid (32, 20), 100 t-rows per block.
// ---------------------------------------------------------------------------
__global__ void ctx_kernel(const int* __restrict__ enc_len) {
    int b = blockIdx.x;
    int t0 = blockIdx.y * 100;
    if (t0 >= enc_len[b]) return;
    int d0 = threadIdx.x * 4;
    float a0 = 0.f, a1 = 0.f, a2 = 0.f, a3 = 0.f;
    const __half* base = g_Ah + (size_t)b * NT * KEXT + d0;
    const float* ab = g_attn + b * NT;

    #pragma unroll 1
    for (int i = 0; i < 25; i++) {
        int t = t0 + i * 4;
        float4 w = *reinterpret_cast<const float4*>(ab + t);
        uint2 v0 = *reinterpret_cast<const uint2*>(base + (size_t)(t + 0) * KEXT);
        uint2 v1 = *reinterpret_cast<const uint2*>(base + (size_t)(t + 1) * KEXT);
        uint2 v2 = *reinterpret_cast<const uint2*>(base + (size_t)(t + 2) * KEXT);
        uint2 v3 = *reinterpret_cast<const uint2*>(base + (size_t)(t + 3) * KEXT);
        float2 p, q;
        p = __half22float2(*reinterpret_cast<__half2*>(&v0.x));
        q = __half22float2(*reinterpret_cast<__half2*>(&v0.y));
        a0 = fmaf(w.x, p.x, a0); a1 = fmaf(w.x, p.y, a1);
        a2 = fmaf(w.x, q.x, a2); a3 = fmaf(w.x, q.y, a3);
        p = __half22float2(*reinterpret_cast<__half2*>(&v1.x));
        q = __half22float2(*reinterpret_cast<__half2*>(&v1.y));
        a0 = fmaf(w.y, p.x, a0); a1 = fmaf(w.y, p.y, a1);
        a2 = fmaf(w.y, q.x, a2); a3 = fmaf(w.y, q.y, a3);
        p = __half22float2(*reinterpret_cast<__half2*>(&v2.x));
        q = __half22float2(*reinterpret_cast<__half2*>(&v2.y));
        a0 = fmaf(w.z, p.x, a0); a1 = fmaf(w.z, p.y, a1);
        a2 = fmaf(w.z, q.x, a2); a3 = fmaf(w.z, q.y, a3);
        p = __half22float2(*reinterpret_cast<__half2*>(&v3.x));
        q = __half22float2(*reinterpret_cast<__half2*>(&v3.y));
        a0 = fmaf(w.w, p.x, a0); a1 = fmaf(w.w, p.y, a1);
        a2 = fmaf(w.w, q.x, a2); a3 = fmaf(w.w, q.y, a3);
    }
    atomicAdd(&g_ctx[b*ED + d0 + 0], a0);
    atomicAdd(&g_ctx[b*ED + d0 + 1], a1);
    atomicAdd(&g_ctx[b*ED + d0 + 2], a2);
    atomicAdd(&g_ctx[b*ED + d0 + 3], a3);
}

// ---------------------------------------------------------------------------
// c[b,o] = ctx[b]@W_o + b_o   (grid 32 x 4)
// ---------------------------------------------------------------------------
__global__ void out_kernel(const float* __restrict__ W_o,
                           const float* __restrict__ b_o,
                           float* __restrict__ c_dst, int write_dst) {
    __shared__ float cs[ED];
    int b = blockIdx.x;
    int o = blockIdx.y * 256 + threadIdx.x;
    for (int d = threadIdx.x; d < ED; d += 256) cs[d] = g_ctx[b*ED + d];
    __syncthreads();
    if (!write_dst) return;
    float acc = b_o[o];
    #pragma unroll 8
    for (int d = 0; d < ED; d++)
        acc = fmaf(cs[d], W_o[d*OD + o], acc);
    c_dst[b*OD + o] = acc;
}

// ---------------------------------------------------------------------------
extern "C" void kernel_launch(void* const* d_in, const int* in_sizes, int n_in,
                              void* d_out, int out_size) {
    const float* enc_pad  = (const float*)d_in[0];
    const int*   enc_len  = (const int*)  d_in[1];
    const float* dec_h    = (const float*)d_in[2];
    const float* att_prev = (const float*)d_in[3];
    const float* W_enc    = (const float*)d_in[4];
    const float* b_enc    = (const float*)d_in[5];
    const float* W_dec    = (const float*)d_in[6];
    const float* b_dec    = (const float*)d_in[7];
    const float* W_att    = (const float*)d_in[8];
    const float* b_att    = (const float*)d_in[9];
    const float* conv_w   = (const float*)d_in[10];
    const float* gvec     = (const float*)d_in[11];
    const float* W_o      = (const float*)d_in[12];
    const float* b_o      = (const float*)d_in[13];

    float* out = (float*)d_out;
    float* c_dst    = out;
    float* attn_dst = out;
    int write_c = 0, write_attn = 0;
    if (out_size >= NB*OD + NB*NT) {
        c_dst = out; attn_dst = out + NB*OD;
        write_c = 1; write_attn = 1;
    } else if (out_size == NB*NT) {
        attn_dst = out; write_attn = 1;
    } else {
        c_dst = out; write_c = 1;
    }

    static int smem_set = 0;
    if (!smem_set) {
        cudaFuncSetAttribute(gemm_e_mma, cudaFuncAttributeMaxDynamicSharedMemorySize, DYN_SMEM);
        smem_set = 1;
    }

    prep_A<<<2256, 256>>>(enc_pad, att_prev, conv_w, enc_len);
    btrans_kernel<<<dim3(KEXT/32, AD/32), dim3(32,32)>>>(W_enc, W_att);
    bias_kernel<<<dim3(NB, 2), 256>>>(dec_h, W_dec, b_dec, b_enc, b_att);
    gemm_e_mma<<<dim3(4, 500), 256, DYN_SMEM>>>(gvec, enc_len);
    softmax_kernel<<<NB, 256>>>(enc_len, attn_dst, write_attn);
    ctx_kernel<<<dim3(NB, 20), 256>>>(enc_len);
    out_kernel<<<dim3(NB, 4), 256>>>(W_o, b_o, c_dst, write_c);
}